// round 1
// baseline (speedup 1.0000x reference)
#include <cuda_runtime.h>
#include <stdint.h>

// ---------------- problem constants ----------------
#define N_USERS  50000
#define N_ITEMS  100000
#define N_NODES  (N_USERS + N_ITEMS)     // 150000
#define N_EDGES  2400000
#define DIM      64
#define N_LAYERS 3
#define BATCH    4096

#define TOTAL    (N_NODES * DIM)         // 9,600,000 floats

// ---------------- scratch (device globals; no allocation allowed) ----------------
__device__ float g_buf0[TOTAL];
__device__ float g_buf1[TOTAL];
__device__ float g_acc [TOTAL];

// ---------------- kernels ----------------

// buf0 = concat(emb_user, emb_item); acc = same; buf1 = 0  (float4 vectorized)
__global__ void init_kernel(const float* __restrict__ eu,
                            const float* __restrict__ ei) {
    int idx = blockIdx.x * blockDim.x + threadIdx.x;          // float4 index
    const int n4 = TOTAL / 4;
    if (idx >= n4) return;
    const int nu4 = (N_USERS * DIM) / 4;
    float4 v;
    if (idx < nu4) v = reinterpret_cast<const float4*>(eu)[idx];
    else           v = reinterpret_cast<const float4*>(ei)[idx - nu4];
    reinterpret_cast<float4*>(g_buf0)[idx] = v;
    reinterpret_cast<float4*>(g_acc )[idx] = v;
    reinterpret_cast<float4*>(g_buf1)[idx] = make_float4(0.f, 0.f, 0.f, 0.f);
}

// y[dst] += vals * x[src]; 16 threads per edge, each handles one float4 chunk.
// Uses red.global.add.v4.f32 (sm_90+): vectorized no-return reduction.
__global__ void spmm_kernel(const float* __restrict__ x,
                            float* __restrict__ y,
                            const float* __restrict__ vals,
                            const int*   __restrict__ src,
                            const int*   __restrict__ dst) {
    long long tid = (long long)blockIdx.x * blockDim.x + threadIdx.x;
    int e = (int)(tid >> 4);
    int c = (int)(tid & 15);
    if (e >= N_EDGES) return;
    float v = vals[e];
    int   s = src[e];
    int   d = dst[e];
    float4 xv = reinterpret_cast<const float4*>(x + (long long)s * DIM)[c];
    xv.x *= v; xv.y *= v; xv.z *= v; xv.w *= v;
    float* yp = y + (long long)d * DIM + c * 4;
    asm volatile("red.global.add.v4.f32 [%0], {%1, %2, %3, %4};"
                 :: "l"(yp), "f"(xv.x), "f"(xv.y), "f"(xv.z), "f"(xv.w)
                 : "memory");
}

// acc += y; optionally zero another buffer (next SpMM target) in the same pass
__global__ void axpy_zero_kernel(const float* __restrict__ y,
                                 float* __restrict__ zero_target) {
    int idx = blockIdx.x * blockDim.x + threadIdx.x;
    const int n4 = TOTAL / 4;
    if (idx >= n4) return;
    float4 a = reinterpret_cast<float4*>(g_acc)[idx];
    float4 b = reinterpret_cast<const float4*>(y)[idx];
    a.x += b.x; a.y += b.y; a.z += b.z; a.w += b.w;
    reinterpret_cast<float4*>(g_acc)[idx] = a;
    if (zero_target)
        reinterpret_cast<float4*>(zero_target)[idx] = make_float4(0.f, 0.f, 0.f, 0.f);
}

// gamma[b] = dot(acc[users[b]], acc[N_USERS+items[b]]) / 16   (/4 per factor)
// one warp per batch element; lane handles a float2 (64 dims / 32 lanes)
__global__ void dot_kernel(const int* __restrict__ users,
                           const int* __restrict__ items,
                           float* __restrict__ out) {
    int warp_in_block = threadIdx.x >> 5;
    int lane = threadIdx.x & 31;
    int b = blockIdx.x * (blockDim.x >> 5) + warp_in_block;
    if (b >= BATCH) return;
    int u = users[b];
    int it = N_USERS + items[b];
    const float2* au = reinterpret_cast<const float2*>(g_acc) + (long long)u  * (DIM / 2);
    const float2* ai = reinterpret_cast<const float2*>(g_acc) + (long long)it * (DIM / 2);
    float2 x = au[lane];
    float2 yv = ai[lane];
    float s = x.x * yv.x + x.y * yv.y;
    #pragma unroll
    for (int off = 16; off > 0; off >>= 1)
        s += __shfl_down_sync(0xFFFFFFFFu, s, off);
    if (lane == 0)
        out[b] = s * (1.0f / ((N_LAYERS + 1) * (N_LAYERS + 1)));  // 1/16
}

// ---------------- launch ----------------
extern "C" void kernel_launch(void* const* d_in, const int* in_sizes, int n_in,
                              void* d_out, int out_size) {
    (void)in_sizes; (void)n_in; (void)out_size;
    const float* emb_user = (const float*)d_in[0];
    const float* emb_item = (const float*)d_in[1];
    const float* vals     = (const float*)d_in[2];
    const int*   src      = (const int*)  d_in[3];
    const int*   dst      = (const int*)  d_in[4];
    const int*   users    = (const int*)  d_in[5];
    const int*   items    = (const int*)  d_in[6];
    float* out = (float*)d_out;

    float *b0, *b1, *acc;
    cudaGetSymbolAddress((void**)&b0,  g_buf0);
    cudaGetSymbolAddress((void**)&b1,  g_buf1);
    cudaGetSymbolAddress((void**)&acc, g_acc);
    (void)acc;

    const int threads = 256;
    const int grid_nd4 = (TOTAL / 4 + threads - 1) / threads;           // elementwise passes
    const long long spmm_threads = (long long)N_EDGES * 16;
    const int grid_spmm = (int)((spmm_threads + threads - 1) / threads);

    // init: b0 = x = emb, acc = emb, b1 (layer-1 target) = 0
    init_kernel<<<grid_nd4, threads>>>(emb_user, emb_item);

    // layer 1: b0 -> b1 ; acc += b1 ; zero b0 (layer-2 target)
    spmm_kernel<<<grid_spmm, threads>>>(b0, b1, vals, src, dst);
    axpy_zero_kernel<<<grid_nd4, threads>>>(b1, b0);

    // layer 2: b1 -> b0 ; acc += b0 ; zero b1 (layer-3 target)
    spmm_kernel<<<grid_spmm, threads>>>(b1, b0, vals, src, dst);
    axpy_zero_kernel<<<grid_nd4, threads>>>(b0, b1);

    // layer 3: b0 -> b1 ; acc += b1 (no zero needed)
    spmm_kernel<<<grid_spmm, threads>>>(b0, b1, vals, src, dst);
    axpy_zero_kernel<<<grid_nd4, threads>>>(b1, nullptr);

    // batched dot: 8 warps per block
    const int dot_threads = 256;
    const int warps_per_block = dot_threads / 32;
    const int grid_dot = (BATCH + warps_per_block - 1) / warps_per_block;
    dot_kernel<<<grid_dot, dot_threads>>>(users, items, out);
}

// round 2
// speedup vs baseline: 1.7970x; 1.7970x over previous
#include <cuda_runtime.h>
#include <stdint.h>

// ---------------- problem constants ----------------
#define N_USERS  50000
#define N_ITEMS  100000
#define N_NODES  (N_USERS + N_ITEMS)     // 150000
#define N_EDGES  2400000
#define DIM      64
#define N_LAYERS 3
#define BATCH    4096

#define TOTAL    (N_NODES * DIM)         // 9,600,000 floats

#define SCAN_B   1024
#define NBLK     ((N_NODES + SCAN_B - 1) / SCAN_B)   // 147

// ---------------- scratch (device globals; no allocation allowed) ----------------
__device__ float g_buf0[TOTAL];
__device__ float g_buf1[TOTAL];
__device__ float g_acc [TOTAL];

__device__ int   g_cnt   [N_NODES];
__device__ int   g_rowptr[N_NODES + 1];
__device__ int   g_woff  [N_NODES];
__device__ int   g_bsum  [256];
__device__ int   g_esrc  [N_EDGES];
__device__ float g_eval  [N_EDGES];

// ---------------- CSR build ----------------

__global__ void zero_cnt_kernel() {
    int i = blockIdx.x * blockDim.x + threadIdx.x;
    if (i < N_NODES) g_cnt[i] = 0;
}

__global__ void hist_kernel(const int* __restrict__ dst) {
    int e = blockIdx.x * blockDim.x + threadIdx.x;
    if (e < N_EDGES) atomicAdd(&g_cnt[dst[e]], 1);
}

// per-block exclusive scan of g_cnt -> g_rowptr (local), block totals -> g_bsum
__global__ void scan_part_kernel() {
    __shared__ int s[SCAN_B];
    int gid = blockIdx.x * SCAN_B + threadIdx.x;
    int v = (gid < N_NODES) ? g_cnt[gid] : 0;
    s[threadIdx.x] = v;
    __syncthreads();
    #pragma unroll
    for (int off = 1; off < SCAN_B; off <<= 1) {
        int t = (threadIdx.x >= off) ? s[threadIdx.x - off] : 0;
        __syncthreads();
        s[threadIdx.x] += t;
        __syncthreads();
    }
    if (gid < N_NODES) g_rowptr[gid] = s[threadIdx.x] - v;   // exclusive (local)
    if (threadIdx.x == SCAN_B - 1) g_bsum[blockIdx.x] = s[threadIdx.x];
}

// single-block exclusive scan of the 147 block sums
__global__ void scan_bsum_kernel() {
    __shared__ int s[256];
    int v = (threadIdx.x < NBLK) ? g_bsum[threadIdx.x] : 0;
    s[threadIdx.x] = v;
    __syncthreads();
    #pragma unroll
    for (int off = 1; off < 256; off <<= 1) {
        int t = (threadIdx.x >= off) ? s[threadIdx.x - off] : 0;
        __syncthreads();
        s[threadIdx.x] += t;
        __syncthreads();
    }
    if (threadIdx.x < NBLK) g_bsum[threadIdx.x] = s[threadIdx.x] - v;  // exclusive
}

__global__ void add_off_kernel() {
    int i = blockIdx.x * blockDim.x + threadIdx.x;
    if (i < N_NODES) {
        int r = g_rowptr[i] + g_bsum[i / SCAN_B];
        g_rowptr[i] = r;
        g_woff[i]   = r;
    }
    if (i == 0) g_rowptr[N_NODES] = N_EDGES;
}

__global__ void scatter_kernel(const int* __restrict__ src,
                               const int* __restrict__ dst,
                               const float* __restrict__ vals) {
    int e = blockIdx.x * blockDim.x + threadIdx.x;
    if (e >= N_EDGES) return;
    int d = dst[e];
    int pos = atomicAdd(&g_woff[d], 1);
    g_esrc[pos] = src[e];
    g_eval[pos] = vals[e];
}

// ---------------- init ----------------
// buf0 = x = concat(emb_user, emb_item); acc = same
__global__ void init_kernel(const float* __restrict__ eu,
                            const float* __restrict__ ei) {
    int idx = blockIdx.x * blockDim.x + threadIdx.x;   // float4 index
    const int n4 = TOTAL / 4;
    if (idx >= n4) return;
    const int nu4 = (N_USERS * DIM) / 4;
    float4 v;
    if (idx < nu4) v = reinterpret_cast<const float4*>(eu)[idx];
    else           v = reinterpret_cast<const float4*>(ei)[idx - nu4];
    reinterpret_cast<float4*>(g_buf0)[idx] = v;
    reinterpret_cast<float4*>(g_acc )[idx] = v;
}

// ---------------- gather SpMM, fused acc += y ----------------
// one warp per dst node; lanes 0-15 handle even edge slot, 16-31 odd slot;
// within a slot, lane c in [0,16) handles float4 chunk c of the 64-dim row.
__global__ void spmm_gather_kernel(const float* __restrict__ x,
                                   float* __restrict__ y) {
    int warp_in_block = threadIdx.x >> 5;
    int node = blockIdx.x * (blockDim.x >> 5) + warp_in_block;
    if (node >= N_NODES) return;
    int lane = threadIdx.x & 31;
    int c    = lane & 15;           // float4 chunk
    int slot = lane >> 4;           // 0 or 1

    int beg = g_rowptr[node];
    int end = g_rowptr[node + 1];

    float4 a = make_float4(0.f, 0.f, 0.f, 0.f);
    #pragma unroll 2
    for (int j = beg + slot; j < end; j += 2) {
        int   s = g_esrc[j];
        float v = g_eval[j];
        float4 xv = reinterpret_cast<const float4*>(x + (long long)s * DIM)[c];
        a.x += v * xv.x; a.y += v * xv.y; a.z += v * xv.z; a.w += v * xv.w;
    }
    // combine the two slots (lane l += lane l+16)
    a.x += __shfl_down_sync(0xFFFFFFFFu, a.x, 16);
    a.y += __shfl_down_sync(0xFFFFFFFFu, a.y, 16);
    a.z += __shfl_down_sync(0xFFFFFFFFu, a.z, 16);
    a.w += __shfl_down_sync(0xFFFFFFFFu, a.w, 16);

    if (slot == 0) {
        long long o = (long long)node * DIM + c * 4;
        reinterpret_cast<float4*>(y + o)[0] = a;
        float4 ac = reinterpret_cast<float4*>(g_acc + o)[0];
        ac.x += a.x; ac.y += a.y; ac.z += a.z; ac.w += a.w;
        reinterpret_cast<float4*>(g_acc + o)[0] = ac;
    }
}

// ---------------- batched dot ----------------
// gamma[b] = dot(acc[u], acc[N_USERS+i]) / 16   ( (1/4)^2 for the mean-pool )
__global__ void dot_kernel(const int* __restrict__ users,
                           const int* __restrict__ items,
                           float* __restrict__ out) {
    int warp_in_block = threadIdx.x >> 5;
    int lane = threadIdx.x & 31;
    int b = blockIdx.x * (blockDim.x >> 5) + warp_in_block;
    if (b >= BATCH) return;
    int u  = users[b];
    int it = N_USERS + items[b];
    const float2* au = reinterpret_cast<const float2*>(g_acc) + (long long)u  * (DIM / 2);
    const float2* ai = reinterpret_cast<const float2*>(g_acc) + (long long)it * (DIM / 2);
    float2 xv = au[lane];
    float2 yv = ai[lane];
    float s = xv.x * yv.x + xv.y * yv.y;
    #pragma unroll
    for (int off = 16; off > 0; off >>= 1)
        s += __shfl_down_sync(0xFFFFFFFFu, s, off);
    if (lane == 0)
        out[b] = s * (1.0f / ((N_LAYERS + 1) * (N_LAYERS + 1)));   // 1/16
}

// ---------------- launch ----------------
extern "C" void kernel_launch(void* const* d_in, const int* in_sizes, int n_in,
                              void* d_out, int out_size) {
    (void)in_sizes; (void)n_in; (void)out_size;
    const float* emb_user = (const float*)d_in[0];
    const float* emb_item = (const float*)d_in[1];
    const float* vals     = (const float*)d_in[2];
    const int*   src      = (const int*)  d_in[3];
    const int*   dst      = (const int*)  d_in[4];
    const int*   users    = (const int*)  d_in[5];
    const int*   items    = (const int*)  d_in[6];
    float* out = (float*)d_out;

    float *b0, *b1;
    cudaGetSymbolAddress((void**)&b0, g_buf0);
    cudaGetSymbolAddress((void**)&b1, g_buf1);

    const int T = 256;
    const int grid_nodes = (N_NODES + T - 1) / T;
    const int grid_edges = (N_EDGES + T - 1) / T;
    const int grid_nd4   = (TOTAL / 4 + T - 1) / T;

    // ---- CSR build (dst-grouped) ----
    zero_cnt_kernel <<<grid_nodes, T>>>();
    hist_kernel     <<<grid_edges, T>>>(dst);
    scan_part_kernel<<<NBLK, SCAN_B>>>();
    scan_bsum_kernel<<<1, 256>>>();
    add_off_kernel  <<<grid_nodes, T>>>();
    scatter_kernel  <<<grid_edges, T>>>(src, dst, vals);

    // ---- init: x = emb, acc = emb ----
    init_kernel<<<grid_nd4, T>>>(emb_user, emb_item);

    // ---- 3 propagation layers, gather + fused acc ----
    const int warps_per_block = T / 32;
    const int grid_spmm = (N_NODES + warps_per_block - 1) / warps_per_block;
    spmm_gather_kernel<<<grid_spmm, T>>>(b0, b1);   // layer 1: b0 -> b1
    spmm_gather_kernel<<<grid_spmm, T>>>(b1, b0);   // layer 2: b1 -> b0
    spmm_gather_kernel<<<grid_spmm, T>>>(b0, b1);   // layer 3: b0 -> b1

    // ---- batched dot ----
    const int grid_dot = (BATCH + warps_per_block - 1) / warps_per_block;
    dot_kernel<<<grid_dot, T>>>(users, items, out);
}

// round 3
// speedup vs baseline: 2.6941x; 1.4992x over previous
#include <cuda_runtime.h>
#include <stdint.h>

// ---------------- problem constants ----------------
#define N_USERS  50000
#define N_ITEMS  100000
#define N_NODES  (N_USERS + N_ITEMS)     // 150000
#define N_EDGES  2400000
#define DIM      64
#define BATCH    4096

#define TOTAL    (N_NODES * DIM)         // 9,600,000 floats

#define SCAN_B   1024
#define NBLK     ((N_NODES + SCAN_B - 1) / SCAN_B)   // 147

// ---------------- scratch (device globals; no allocation allowed) ----------------
__device__ float g_x1[TOTAL];            // layer-1 output
__device__ float g_x2[TOTAL];            // layer-2 output

__device__ int2  g_edge  [N_EDGES];      // packed (src, val) grouped by dst
__device__ int   g_cnt   [N_NODES];
__device__ int   g_rowptr[N_NODES + 1];
__device__ int   g_woff  [N_NODES];
__device__ int   g_bsum  [256];

// ---------------- CSR build ----------------

__global__ void zero_cnt_kernel() {
    int i = blockIdx.x * blockDim.x + threadIdx.x;
    if (i < N_NODES) g_cnt[i] = 0;
}

__global__ void hist_kernel(const int* __restrict__ dst) {
    int e = blockIdx.x * blockDim.x + threadIdx.x;
    if (e < N_EDGES) atomicAdd(&g_cnt[dst[e]], 1);
}

// per-block exclusive scan of g_cnt -> g_rowptr (local); block totals -> g_bsum
// warp-shuffle scan: 1024 threads = 32 warps
__global__ void scan_part_kernel() {
    __shared__ int warp_tot[32];
    int gid  = blockIdx.x * SCAN_B + threadIdx.x;
    int lane = threadIdx.x & 31;
    int wid  = threadIdx.x >> 5;
    int v = (gid < N_NODES) ? g_cnt[gid] : 0;
    int inc = v;
    #pragma unroll
    for (int off = 1; off < 32; off <<= 1) {
        int t = __shfl_up_sync(0xFFFFFFFFu, inc, off);
        if (lane >= off) inc += t;
    }
    if (lane == 31) warp_tot[wid] = inc;
    __syncthreads();
    if (wid == 0) {
        int t = warp_tot[lane];
        int s = t;
        #pragma unroll
        for (int off = 1; off < 32; off <<= 1) {
            int u = __shfl_up_sync(0xFFFFFFFFu, s, off);
            if (lane >= off) s += u;
        }
        warp_tot[lane] = s - t;   // exclusive warp offsets
    }
    __syncthreads();
    int ex = inc - v + warp_tot[wid];          // exclusive within block
    if (gid < N_NODES) g_rowptr[gid] = ex;
    if (threadIdx.x == SCAN_B - 1) g_bsum[blockIdx.x] = ex + v;  // block total
}

// single-block exclusive scan of the 147 block totals
__global__ void scan_bsum_kernel() {
    __shared__ int s[256];
    int v = (threadIdx.x < NBLK) ? g_bsum[threadIdx.x] : 0;
    s[threadIdx.x] = v;
    __syncthreads();
    #pragma unroll
    for (int off = 1; off < 256; off <<= 1) {
        int t = (threadIdx.x >= off) ? s[threadIdx.x - off] : 0;
        __syncthreads();
        s[threadIdx.x] += t;
        __syncthreads();
    }
    if (threadIdx.x < NBLK) g_bsum[threadIdx.x] = s[threadIdx.x] - v;
}

__global__ void add_off_kernel() {
    int i = blockIdx.x * blockDim.x + threadIdx.x;
    if (i < N_NODES) {
        int r = g_rowptr[i] + g_bsum[i / SCAN_B];
        g_rowptr[i] = r;
        g_woff[i]   = r;
    }
    if (i == 0) g_rowptr[N_NODES] = N_EDGES;
}

__global__ void scatter_kernel(const int* __restrict__ src,
                               const int* __restrict__ dst,
                               const float* __restrict__ vals) {
    int e = blockIdx.x * blockDim.x + threadIdx.x;
    if (e >= N_EDGES) return;
    int d = dst[e];
    int pos = atomicAdd(&g_woff[d], 1);
    g_edge[pos] = make_int2(src[e], __float_as_int(vals[e]));
}

// ---------------- gather SpMM ----------------
// one warp per dst node; slot = lane>>4 picks even/odd edge; c = lane&15 picks
// the float4 chunk of the 64-dim row.  FROM_EMB: x is concat(eu, ei) virtually.
template<bool FROM_EMB>
__global__ void spmm_gather_kernel(const float* __restrict__ x,
                                   float* __restrict__ y,
                                   const float* __restrict__ eu,
                                   const float* __restrict__ ei) {
    int node = blockIdx.x * (blockDim.x >> 5) + (threadIdx.x >> 5);
    if (node >= N_NODES) return;
    int lane = threadIdx.x & 31;
    int c    = lane & 15;
    int slot = lane >> 4;

    int beg = g_rowptr[node];
    int end = g_rowptr[node + 1];

    float4 a = make_float4(0.f, 0.f, 0.f, 0.f);
    #pragma unroll 2
    for (int j = beg + slot; j < end; j += 2) {
        int2  ed = g_edge[j];
        float v  = __int_as_float(ed.y);
        const float* base;
        if (FROM_EMB)
            base = (ed.x < N_USERS) ? eu + (long long)ed.x * DIM
                                    : ei + (long long)(ed.x - N_USERS) * DIM;
        else
            base = x + (long long)ed.x * DIM;
        float4 xv = reinterpret_cast<const float4*>(base)[c];
        a.x += v * xv.x; a.y += v * xv.y; a.z += v * xv.z; a.w += v * xv.w;
    }
    a.x += __shfl_down_sync(0xFFFFFFFFu, a.x, 16);
    a.y += __shfl_down_sync(0xFFFFFFFFu, a.y, 16);
    a.z += __shfl_down_sync(0xFFFFFFFFu, a.z, 16);
    a.w += __shfl_down_sync(0xFFFFFFFFu, a.w, 16);

    if (slot == 0)
        reinterpret_cast<float4*>(y + (long long)node * DIM + c * 4)[0] = a;
}

// ---------------- fused layer-3 gather + dot ----------------
// one warp per batch element: gathers x3 rows for its user and item nodes
// directly from x2, adds emb + x1 + x2 base rows, dots, scales by 1/16.
__device__ __forceinline__ float4 gather3_chunk(const float* __restrict__ x2,
                                                int node, int c, int slot) {
    int beg = g_rowptr[node];
    int end = g_rowptr[node + 1];
    float4 a = make_float4(0.f, 0.f, 0.f, 0.f);
    #pragma unroll 2
    for (int j = beg + slot; j < end; j += 2) {
        int2  ed = g_edge[j];
        float v  = __int_as_float(ed.y);
        float4 xv = reinterpret_cast<const float4*>(x2 + (long long)ed.x * DIM)[c];
        a.x += v * xv.x; a.y += v * xv.y; a.z += v * xv.z; a.w += v * xv.w;
    }
    // xor-combine the two slots so ALL lanes hold the full chunk sum
    a.x += __shfl_xor_sync(0xFFFFFFFFu, a.x, 16);
    a.y += __shfl_xor_sync(0xFFFFFFFFu, a.y, 16);
    a.z += __shfl_xor_sync(0xFFFFFFFFu, a.z, 16);
    a.w += __shfl_xor_sync(0xFFFFFFFFu, a.w, 16);
    return a;
}

__global__ void dot_fused_kernel(const int* __restrict__ users,
                                 const int* __restrict__ items,
                                 const float* __restrict__ eu,
                                 const float* __restrict__ ei,
                                 float* __restrict__ out) {
    int b = blockIdx.x * (blockDim.x >> 5) + (threadIdx.x >> 5);
    if (b >= BATCH) return;
    int lane = threadIdx.x & 31;
    int c    = lane & 15;
    int slot = lane >> 4;

    int u  = users[b];
    int ni = N_USERS + items[b];

    float4 gu = gather3_chunk(g_x2, u,  c, slot);
    float4 gi = gather3_chunk(g_x2, ni, c, slot);

    long long ou = (long long)u  * DIM + c * 4;
    long long oi = (long long)ni * DIM + c * 4;

    float4 bu = reinterpret_cast<const float4*>(eu + (long long)u * DIM + c * 4)[0];
    float4 bi = reinterpret_cast<const float4*>(ei + (long long)items[b] * DIM + c * 4)[0];
    float4 u1 = reinterpret_cast<const float4*>(g_x1 + ou)[0];
    float4 i1 = reinterpret_cast<const float4*>(g_x1 + oi)[0];
    float4 u2 = reinterpret_cast<const float4*>(g_x2 + ou)[0];
    float4 i2 = reinterpret_cast<const float4*>(g_x2 + oi)[0];

    float4 ru = make_float4(bu.x + u1.x + u2.x + gu.x,
                            bu.y + u1.y + u2.y + gu.y,
                            bu.z + u1.z + u2.z + gu.z,
                            bu.w + u1.w + u2.w + gu.w);
    float4 ri = make_float4(bi.x + i1.x + i2.x + gi.x,
                            bi.y + i1.y + i2.y + gi.y,
                            bi.z + i1.z + i2.z + gi.z,
                            bi.w + i1.w + i2.w + gi.w);

    float p = ru.x * ri.x + ru.y * ri.y + ru.z * ri.z + ru.w * ri.w;
    #pragma unroll
    for (int off = 8; off > 0; off >>= 1)
        p += __shfl_xor_sync(0xFFFFFFFFu, p, off);

    if (lane == 0)
        out[b] = p * (1.0f / 16.0f);     // (1/4)^2 mean-pool factors
}

// ---------------- launch ----------------
extern "C" void kernel_launch(void* const* d_in, const int* in_sizes, int n_in,
                              void* d_out, int out_size) {
    (void)in_sizes; (void)n_in; (void)out_size;
    const float* emb_user = (const float*)d_in[0];
    const float* emb_item = (const float*)d_in[1];
    const float* vals     = (const float*)d_in[2];
    const int*   src      = (const int*)  d_in[3];
    const int*   dst      = (const int*)  d_in[4];
    const int*   users    = (const int*)  d_in[5];
    const int*   items    = (const int*)  d_in[6];
    float* out = (float*)d_out;

    float *x1, *x2;
    cudaGetSymbolAddress((void**)&x1, g_x1);
    cudaGetSymbolAddress((void**)&x2, g_x2);

    const int T = 256;
    const int grid_nodes = (N_NODES + T - 1) / T;
    const int grid_edges = (N_EDGES + T - 1) / T;

    // ---- CSR build (dst-grouped, packed edges) ----
    zero_cnt_kernel <<<grid_nodes, T>>>();
    hist_kernel     <<<grid_edges, T>>>(dst);
    scan_part_kernel<<<NBLK, SCAN_B>>>();
    scan_bsum_kernel<<<1, 256>>>();
    add_off_kernel  <<<grid_nodes, T>>>();
    scatter_kernel  <<<grid_edges, T>>>(src, dst, vals);

    // ---- propagation ----
    const int wpb = T / 32;
    const int grid_spmm = (N_NODES + wpb - 1) / wpb;
    spmm_gather_kernel<true ><<<grid_spmm, T>>>(nullptr, x1, emb_user, emb_item); // layer 1
    spmm_gather_kernel<false><<<grid_spmm, T>>>(x1, x2, nullptr, nullptr);        // layer 2

    // ---- layer 3 fused with batched dot ----
    const int grid_dot = (BATCH + wpb - 1) / wpb;
    dot_fused_kernel<<<grid_dot, T>>>(users, items, emb_user, emb_item, out);
}

// round 4
// speedup vs baseline: 2.9268x; 1.0864x over previous
#include <cuda_runtime.h>
#include <cuda_fp16.h>
#include <stdint.h>

// ---------------- problem constants ----------------
#define N_USERS  50000
#define N_ITEMS  100000
#define N_NODES  (N_USERS + N_ITEMS)     // 150000
#define N_EDGES  2400000
#define DIM      64
#define BATCH    4096

#define TOTAL    (N_NODES * DIM)         // 9,600,000 floats
#define TOT8     (TOTAL / 8)             // uint4-of-half count per buffer

#define SCAN_B   1024
#define NBLK     ((N_NODES + SCAN_B - 1) / SCAN_B)   // 147

// ---------------- scratch (device globals; no allocation allowed) ----------------
__device__ uint4 g_e16[TOT8];            // emb (fp16), layer-0 state
__device__ uint4 g_x1 [TOT8];            // layer-1 output (fp16)
__device__ uint4 g_x2 [TOT8];            // layer-2 output (fp16)

__device__ int2  g_edge  [N_EDGES];      // packed (src, val_fp32) grouped by dst
__device__ int   g_cnt   [N_NODES];
__device__ int   g_rowptr[N_NODES + 1];
__device__ int   g_woff  [N_NODES];
__device__ int   g_bsum  [256];

// ---------------- helpers ----------------
__device__ __forceinline__ unsigned pack_h2(float a, float b) {
    __half2 h = __floats2half2_rn(a, b);
    return *reinterpret_cast<unsigned*>(&h);
}
__device__ __forceinline__ float2 unpack_h2(unsigned u) {
    return __half22float2(*reinterpret_cast<__half2*>(&u));
}

// ---------------- CSR build ----------------

__global__ void hist_kernel(const int* __restrict__ dst) {
    int e = blockIdx.x * blockDim.x + threadIdx.x;
    if (e < N_EDGES) atomicAdd(&g_cnt[dst[e]], 1);
}

// per-block exclusive scan of g_cnt -> g_rowptr (local); block totals -> g_bsum
__global__ void scan_part_kernel() {
    __shared__ int warp_tot[32];
    int gid  = blockIdx.x * SCAN_B + threadIdx.x;
    int lane = threadIdx.x & 31;
    int wid  = threadIdx.x >> 5;
    int v = (gid < N_NODES) ? g_cnt[gid] : 0;
    int inc = v;
    #pragma unroll
    for (int off = 1; off < 32; off <<= 1) {
        int t = __shfl_up_sync(0xFFFFFFFFu, inc, off);
        if (lane >= off) inc += t;
    }
    if (lane == 31) warp_tot[wid] = inc;
    __syncthreads();
    if (wid == 0) {
        int t = warp_tot[lane];
        int s = t;
        #pragma unroll
        for (int off = 1; off < 32; off <<= 1) {
            int u = __shfl_up_sync(0xFFFFFFFFu, s, off);
            if (lane >= off) s += u;
        }
        warp_tot[lane] = s - t;
    }
    __syncthreads();
    int ex = inc - v + warp_tot[wid];
    if (gid < N_NODES) g_rowptr[gid] = ex;
    if (threadIdx.x == SCAN_B - 1) g_bsum[blockIdx.x] = ex + v;
}

// single-block exclusive scan of the 147 block totals (shuffle + tiny serial)
__global__ void scan_bsum_kernel() {
    __shared__ int wt[8];
    int lane = threadIdx.x & 31;
    int wid  = threadIdx.x >> 5;
    int v = (threadIdx.x < NBLK) ? g_bsum[threadIdx.x] : 0;
    int inc = v;
    #pragma unroll
    for (int off = 1; off < 32; off <<= 1) {
        int t = __shfl_up_sync(0xFFFFFFFFu, inc, off);
        if (lane >= off) inc += t;
    }
    if (lane == 31) wt[wid] = inc;
    __syncthreads();
    if (threadIdx.x == 0) {
        int run = 0;
        #pragma unroll
        for (int w = 0; w < 8; w++) { int t = wt[w]; wt[w] = run; run += t; }
    }
    __syncthreads();
    if (threadIdx.x < NBLK) g_bsum[threadIdx.x] = inc - v + wt[wid];
}

__global__ void add_off_kernel() {
    int i = blockIdx.x * blockDim.x + threadIdx.x;
    if (i < N_NODES) {
        int r = g_rowptr[i] + g_bsum[i / SCAN_B];
        g_rowptr[i] = r;
        g_woff[i]   = r;
    }
    if (i == 0) g_rowptr[N_NODES] = N_EDGES;
}

__global__ void scatter_kernel(const int* __restrict__ src,
                               const int* __restrict__ dst,
                               const float* __restrict__ vals) {
    int e = blockIdx.x * blockDim.x + threadIdx.x;
    if (e >= N_EDGES) return;
    int d = dst[e];
    int pos = atomicAdd(&g_woff[d], 1);
    g_edge[pos] = make_int2(src[e], __float_as_int(vals[e]));
}

// ---------------- emb fp32 -> fp16 convert ----------------
__global__ void convert_kernel(const float* __restrict__ eu,
                               const float* __restrict__ ei) {
    int idx = blockIdx.x * blockDim.x + threadIdx.x;    // uint4 index (8 halfs)
    if (idx >= TOT8) return;
    const int nu8 = (N_USERS * DIM) / 8;
    const float4* s;
    if (idx < nu8) s = reinterpret_cast<const float4*>(eu) + (size_t)idx * 2;
    else           s = reinterpret_cast<const float4*>(ei) + (size_t)(idx - nu8) * 2;
    float4 a = s[0], b = s[1];
    uint4 o;
    o.x = pack_h2(a.x, a.y);
    o.y = pack_h2(a.z, a.w);
    o.z = pack_h2(b.x, b.y);
    o.w = pack_h2(b.z, b.w);
    g_e16[idx] = o;
}

// ---------------- gather SpMM (fp16 state, fp32 accumulate) ----------------
// one warp per dst node; c = lane&7 picks the 16B chunk (8 halfs) of the row,
// slot = lane>>3 in [0,4) picks one of 4 parallel edges per iteration.
__global__ void spmm_half_kernel(const uint4* __restrict__ x,
                                 uint4* __restrict__ y) {
    int node = blockIdx.x * (blockDim.x >> 5) + (threadIdx.x >> 5);
    if (node >= N_NODES) return;
    int lane = threadIdx.x & 31;
    int c    = lane & 7;
    int slot = lane >> 3;

    int beg = g_rowptr[node];
    int end = g_rowptr[node + 1];

    float a0 = 0.f, a1 = 0.f, a2 = 0.f, a3 = 0.f,
          a4 = 0.f, a5 = 0.f, a6 = 0.f, a7 = 0.f;

    for (int j = beg + slot; j < end; j += 4) {
        int2  ed = g_edge[j];
        float v  = __int_as_float(ed.y);
        uint4 h  = x[ed.x * 8 + c];
        float2 f0 = unpack_h2(h.x);
        float2 f1 = unpack_h2(h.y);
        float2 f2 = unpack_h2(h.z);
        float2 f3 = unpack_h2(h.w);
        a0 += v * f0.x; a1 += v * f0.y;
        a2 += v * f1.x; a3 += v * f1.y;
        a4 += v * f2.x; a5 += v * f2.y;
        a6 += v * f3.x; a7 += v * f3.y;
    }
    // combine the 4 slots
    #pragma unroll
    for (int off = 8; off <= 16; off <<= 1) {
        a0 += __shfl_xor_sync(0xFFFFFFFFu, a0, off);
        a1 += __shfl_xor_sync(0xFFFFFFFFu, a1, off);
        a2 += __shfl_xor_sync(0xFFFFFFFFu, a2, off);
        a3 += __shfl_xor_sync(0xFFFFFFFFu, a3, off);
        a4 += __shfl_xor_sync(0xFFFFFFFFu, a4, off);
        a5 += __shfl_xor_sync(0xFFFFFFFFu, a5, off);
        a6 += __shfl_xor_sync(0xFFFFFFFFu, a6, off);
        a7 += __shfl_xor_sync(0xFFFFFFFFu, a7, off);
    }
    if (slot == 0) {
        uint4 o;
        o.x = pack_h2(a0, a1);
        o.y = pack_h2(a2, a3);
        o.z = pack_h2(a4, a5);
        o.w = pack_h2(a6, a7);
        y[node * 8 + c] = o;
    }
}

// ---------------- fused layer-3 gather + dot ----------------
// gathers node's layer-3 row chunk from x2 (fp16) into fp32; all lanes end
// up holding the chunk for their c = lane&7.
__device__ __forceinline__ void gather3_chunk(const uint4* __restrict__ x2,
                                              int node, int c, int slot,
                                              float (&g)[8]) {
    int beg = g_rowptr[node];
    int end = g_rowptr[node + 1];
    #pragma unroll
    for (int k = 0; k < 8; k++) g[k] = 0.f;
    for (int j = beg + slot; j < end; j += 4) {
        int2  ed = g_edge[j];
        float v  = __int_as_float(ed.y);
        uint4 h  = x2[ed.x * 8 + c];
        float2 f0 = unpack_h2(h.x);
        float2 f1 = unpack_h2(h.y);
        float2 f2 = unpack_h2(h.z);
        float2 f3 = unpack_h2(h.w);
        g[0] += v * f0.x; g[1] += v * f0.y;
        g[2] += v * f1.x; g[3] += v * f1.y;
        g[4] += v * f2.x; g[5] += v * f2.y;
        g[6] += v * f3.x; g[7] += v * f3.y;
    }
    #pragma unroll
    for (int k = 0; k < 8; k++) {
        g[k] += __shfl_xor_sync(0xFFFFFFFFu, g[k], 8);
        g[k] += __shfl_xor_sync(0xFFFFFFFFu, g[k], 16);
    }
}

__global__ void dot_fused_kernel(const int* __restrict__ users,
                                 const int* __restrict__ items,
                                 const float* __restrict__ eu,
                                 const float* __restrict__ ei,
                                 float* __restrict__ out) {
    int b = blockIdx.x * (blockDim.x >> 5) + (threadIdx.x >> 5);
    if (b >= BATCH) return;
    int lane = threadIdx.x & 31;
    int c    = lane & 7;
    int slot = lane >> 3;

    int u  = users[b];
    int im = items[b];
    int ni = N_USERS + im;

    float gu[8], gi[8];
    gather3_chunk(g_x2, u,  c, slot, gu);
    gather3_chunk(g_x2, ni, c, slot, gi);

    // base terms (replicated across the 4 slot groups — identical reads)
    const float4* pu = reinterpret_cast<const float4*>(eu + u  * DIM + c * 8);
    const float4* pi = reinterpret_cast<const float4*>(ei + im * DIM + c * 8);
    float4 bu0 = pu[0], bu1 = pu[1];
    float4 bi0 = pi[0], bi1 = pi[1];

    uint4 u1h = g_x1[u  * 8 + c], u2h = g_x2[u  * 8 + c];
    uint4 i1h = g_x1[ni * 8 + c], i2h = g_x2[ni * 8 + c];

    float ru[8], ri[8];
    {
        float2 t;
        t = unpack_h2(u1h.x); ru[0] = bu0.x + t.x; ru[1] = bu0.y + t.y;
        t = unpack_h2(u1h.y); ru[2] = bu0.z + t.x; ru[3] = bu0.w + t.y;
        t = unpack_h2(u1h.z); ru[4] = bu1.x + t.x; ru[5] = bu1.y + t.y;
        t = unpack_h2(u1h.w); ru[6] = bu1.z + t.x; ru[7] = bu1.w + t.y;
        t = unpack_h2(u2h.x); ru[0] += t.x; ru[1] += t.y;
        t = unpack_h2(u2h.y); ru[2] += t.x; ru[3] += t.y;
        t = unpack_h2(u2h.z); ru[4] += t.x; ru[5] += t.y;
        t = unpack_h2(u2h.w); ru[6] += t.x; ru[7] += t.y;

        t = unpack_h2(i1h.x); ri[0] = bi0.x + t.x; ri[1] = bi0.y + t.y;
        t = unpack_h2(i1h.y); ri[2] = bi0.z + t.x; ri[3] = bi0.w + t.y;
        t = unpack_h2(i1h.z); ri[4] = bi1.x + t.x; ri[5] = bi1.y + t.y;
        t = unpack_h2(i1h.w); ri[6] = bi1.z + t.x; ri[7] = bi1.w + t.y;
        t = unpack_h2(i2h.x); ri[0] += t.x; ri[1] += t.y;
        t = unpack_h2(i2h.y); ri[2] += t.x; ri[3] += t.y;
        t = unpack_h2(i2h.z); ri[4] += t.x; ri[5] += t.y;
        t = unpack_h2(i2h.w); ri[6] += t.x; ri[7] += t.y;
    }

    float p = 0.f;
    #pragma unroll
    for (int k = 0; k < 8; k++)
        p += (ru[k] + gu[k]) * (ri[k] + gi[k]);

    // p is replicated across the 4 slot groups; reduce over the 8 c-lanes
    p += __shfl_xor_sync(0xFFFFFFFFu, p, 1);
    p += __shfl_xor_sync(0xFFFFFFFFu, p, 2);
    p += __shfl_xor_sync(0xFFFFFFFFu, p, 4);

    if (lane == 0)
        out[b] = p * (1.0f / 16.0f);     // (1/4)^2 mean-pool factors
}

// ---------------- launch ----------------
extern "C" void kernel_launch(void* const* d_in, const int* in_sizes, int n_in,
                              void* d_out, int out_size) {
    (void)in_sizes; (void)n_in; (void)out_size;
    const float* emb_user = (const float*)d_in[0];
    const float* emb_item = (const float*)d_in[1];
    const float* vals     = (const float*)d_in[2];
    const int*   src      = (const int*)  d_in[3];
    const int*   dst      = (const int*)  d_in[4];
    const int*   users    = (const int*)  d_in[5];
    const int*   items    = (const int*)  d_in[6];
    float* out = (float*)d_out;

    uint4 *e16, *x1, *x2;
    int* cnt;
    cudaGetSymbolAddress((void**)&e16, g_e16);
    cudaGetSymbolAddress((void**)&x1,  g_x1);
    cudaGetSymbolAddress((void**)&x2,  g_x2);
    cudaGetSymbolAddress((void**)&cnt, g_cnt);

    const int T = 256;
    const int grid_nodes = (N_NODES + T - 1) / T;
    const int grid_edges = (N_EDGES + T - 1) / T;
    const int grid_cvt   = (TOT8 + T - 1) / T;

    // ---- emb -> fp16 propagation state ----
    convert_kernel<<<grid_cvt, T>>>(emb_user, emb_item);

    // ---- CSR build (dst-grouped, packed edges) ----
    cudaMemsetAsync(cnt, 0, N_NODES * sizeof(int), 0);
    hist_kernel     <<<grid_edges, T>>>(dst);
    scan_part_kernel<<<NBLK, SCAN_B>>>();
    scan_bsum_kernel<<<1, 256>>>();
    add_off_kernel  <<<grid_nodes, T>>>();
    scatter_kernel  <<<grid_edges, T>>>(src, dst, vals);

    // ---- propagation (fp16 gather, fp32 accumulate) ----
    const int wpb = T / 32;
    const int grid_spmm = (N_NODES + wpb - 1) / wpb;
    spmm_half_kernel<<<grid_spmm, T>>>(e16, x1);   // layer 1
    spmm_half_kernel<<<grid_spmm, T>>>(x1,  x2);   // layer 2

    // ---- layer 3 fused with batched dot ----
    const int grid_dot = (BATCH + wpb - 1) / wpb;
    dot_fused_kernel<<<grid_dot, T>>>(users, items, emb_user, emb_item, out);
}

// round 5
// speedup vs baseline: 3.1137x; 1.0639x over previous
#include <cuda_runtime.h>
#include <cuda_fp16.h>
#include <stdint.h>

// ---------------- problem constants ----------------
#define N_USERS  50000
#define N_ITEMS  100000
#define N_NODES  (N_USERS + N_ITEMS)     // 150000
#define N_EDGES  2400000
#define DIM      64
#define BATCH    4096

#define TOTAL    (N_NODES * DIM)         // 9,600,000 floats
#define TOT8     (TOTAL / 8)             // uint4-of-half count per buffer

#define SCAN_B   1024
#define NBLK     ((N_NODES + SCAN_B - 1) / SCAN_B)   // 147

#define FLG_AGG  (1ULL << 62)
#define FLG_INC  (2ULL << 62)

// ---------------- scratch (device globals; no allocation allowed) ----------------
__device__ uint4 g_e16[TOT8];            // emb (fp16), layer-0 state
__device__ uint4 g_x1 [TOT8];            // layer-1 output (fp16)
__device__ uint4 g_x2 [TOT8];            // layer-2 output (fp16)

__device__ int2  g_edge  [N_EDGES];      // packed (src, val_fp32) grouped by dst
__device__ int   g_cnt   [N_NODES];
__device__ int   g_rowptr[N_NODES + 1];
__device__ unsigned long long g_part[NBLK];   // decoupled-lookback scan state

// ---------------- helpers ----------------
__device__ __forceinline__ unsigned pack_h2(float a, float b) {
    __half2 h = __floats2half2_rn(a, b);
    return *reinterpret_cast<unsigned*>(&h);
}
__device__ __forceinline__ float2 unpack_h2(unsigned u) {
    return __half22float2(*reinterpret_cast<__half2*>(&u));
}

// ---------------- convert emb -> fp16 state, and zero scan scratch ----------------
__global__ void convert_kernel(const float* __restrict__ eu,
                               const float* __restrict__ ei) {
    int idx = blockIdx.x * blockDim.x + threadIdx.x;    // uint4 index (8 halfs)
    if (idx < N_NODES) g_cnt[idx] = 0;
    if (idx < NBLK)    g_part[idx] = 0ULL;
    if (idx >= TOT8) return;
    const int nu8 = (N_USERS * DIM) / 8;
    const float4* s;
    if (idx < nu8) s = reinterpret_cast<const float4*>(eu) + (size_t)idx * 2;
    else           s = reinterpret_cast<const float4*>(ei) + (size_t)(idx - nu8) * 2;
    float4 a = s[0], b = s[1];
    uint4 o;
    o.x = pack_h2(a.x, a.y);
    o.y = pack_h2(a.z, a.w);
    o.z = pack_h2(b.x, b.y);
    o.w = pack_h2(b.z, b.w);
    g_e16[idx] = o;
}

// ---------------- histogram (4 edges per thread) ----------------
__global__ void hist_kernel(const int* __restrict__ dst) {
    int t = blockIdx.x * blockDim.x + threadIdx.x;
    int e = t * 4;
    if (e + 3 < N_EDGES) {
        int4 d = reinterpret_cast<const int4*>(dst)[t];
        atomicAdd(&g_cnt[d.x], 1);
        atomicAdd(&g_cnt[d.y], 1);
        atomicAdd(&g_cnt[d.z], 1);
        atomicAdd(&g_cnt[d.w], 1);
    } else {
        for (; e < N_EDGES; e++) atomicAdd(&g_cnt[dst[e]], 1);
    }
}

// ---------------- one-pass decoupled-lookback exclusive scan ----------------
// rowptr[i] = sum of cnt[0..i).  147 blocks, all resident in wave 1.
__global__ void scan_kernel() {
    __shared__ int warp_tot[32];
    __shared__ int s_prefix;
    int b    = blockIdx.x;
    int gid  = b * SCAN_B + threadIdx.x;
    int lane = threadIdx.x & 31;
    int wid  = threadIdx.x >> 5;

    int v = (gid < N_NODES) ? g_cnt[gid] : 0;
    int inc = v;
    #pragma unroll
    for (int off = 1; off < 32; off <<= 1) {
        int t = __shfl_up_sync(0xFFFFFFFFu, inc, off);
        if (lane >= off) inc += t;
    }
    if (lane == 31) warp_tot[wid] = inc;
    __syncthreads();
    if (wid == 0) {
        int t = warp_tot[lane];
        int s = t;
        #pragma unroll
        for (int off = 1; off < 32; off <<= 1) {
            int u = __shfl_up_sync(0xFFFFFFFFu, s, off);
            if (lane >= off) s += u;
        }
        warp_tot[lane] = s - t;   // exclusive warp offsets
    }
    __syncthreads();
    int ex    = inc - v + warp_tot[wid];               // exclusive within block
    int total = warp_tot[31] + __shfl_sync(0xFFFFFFFFu, inc, 31, 32);
    // broadcast of block total: compute from last warp's last lane via smem
    __shared__ int s_total;
    if (threadIdx.x == SCAN_B - 1) s_total = ex + v;
    __syncthreads();
    total = s_total;

    if (threadIdx.x == 0) {
        if (b == 0) {
            atomicExch(&g_part[0], FLG_INC | (unsigned long long)(unsigned)total);
            s_prefix = 0;
        } else {
            atomicExch(&g_part[b], FLG_AGG | (unsigned long long)(unsigned)total);
            int run = 0;
            int p = b - 1;
            while (true) {
                unsigned long long st = atomicAdd(&g_part[p], 0ULL);
                unsigned long long flg = st & (3ULL << 62);
                if (flg == FLG_INC) { run += (int)(unsigned)st; break; }
                if (flg == FLG_AGG) { run += (int)(unsigned)st; p--; }
                // else spin
            }
            atomicExch(&g_part[b],
                       FLG_INC | (unsigned long long)(unsigned)(run + total));
            s_prefix = run;
        }
    }
    __syncthreads();
    int prefix = s_prefix;
    if (gid < N_NODES) g_rowptr[gid] = ex + prefix;
    if (b == NBLK - 1 && threadIdx.x == 0) g_rowptr[N_NODES] = N_EDGES;
}

// ---------------- scatter (countdown on g_cnt; 4 edges per thread) ----------------
__global__ void scatter_kernel(const int* __restrict__ src,
                               const int* __restrict__ dst,
                               const float* __restrict__ vals) {
    int t = blockIdx.x * blockDim.x + threadIdx.x;
    int e = t * 4;
    if (e + 3 < N_EDGES) {
        int4   s4 = reinterpret_cast<const int4*>(src)[t];
        int4   d4 = reinterpret_cast<const int4*>(dst)[t];
        float4 v4 = reinterpret_cast<const float4*>(vals)[t];
        int p;
        p = g_rowptr[d4.x] + atomicSub(&g_cnt[d4.x], 1) - 1;
        g_edge[p] = make_int2(s4.x, __float_as_int(v4.x));
        p = g_rowptr[d4.y] + atomicSub(&g_cnt[d4.y], 1) - 1;
        g_edge[p] = make_int2(s4.y, __float_as_int(v4.y));
        p = g_rowptr[d4.z] + atomicSub(&g_cnt[d4.z], 1) - 1;
        g_edge[p] = make_int2(s4.z, __float_as_int(v4.z));
        p = g_rowptr[d4.w] + atomicSub(&g_cnt[d4.w], 1) - 1;
        g_edge[p] = make_int2(s4.w, __float_as_int(v4.w));
    } else {
        for (; e < N_EDGES; e++) {
            int d = dst[e];
            int p = g_rowptr[d] + atomicSub(&g_cnt[d], 1) - 1;
            g_edge[p] = make_int2(src[e], __float_as_int(vals[e]));
        }
    }
}

// ---------------- gather SpMM (fp16 state, fp32 accumulate) ----------------
// one warp per dst node; c = lane&7 picks the 16B chunk (8 halfs) of the row,
// slot = lane>>3 in [0,4) picks one of 4 parallel edges; inner loop manually
// unrolled 2x so each lane keeps 2 independent gathers in flight.
__global__ void __launch_bounds__(256) spmm_half_kernel(
        const uint4* __restrict__ x, uint4* __restrict__ y) {
    int node = blockIdx.x * (blockDim.x >> 5) + (threadIdx.x >> 5);
    if (node >= N_NODES) return;
    int lane = threadIdx.x & 31;
    int c    = lane & 7;
    int slot = lane >> 3;

    int beg = g_rowptr[node];
    int end = g_rowptr[node + 1];

    float a[8];
    #pragma unroll
    for (int k = 0; k < 8; k++) a[k] = 0.f;

    int j = beg + slot;
    for (; j + 4 < end; j += 8) {
        int2  e0 = g_edge[j];
        int2  e1 = g_edge[j + 4];
        uint4 h0 = x[e0.x * 8 + c];
        uint4 h1 = x[e1.x * 8 + c];
        float v0 = __int_as_float(e0.y);
        float v1 = __int_as_float(e1.y);
        float2 f;
        f = unpack_h2(h0.x); a[0] += v0 * f.x; a[1] += v0 * f.y;
        f = unpack_h2(h0.y); a[2] += v0 * f.x; a[3] += v0 * f.y;
        f = unpack_h2(h0.z); a[4] += v0 * f.x; a[5] += v0 * f.y;
        f = unpack_h2(h0.w); a[6] += v0 * f.x; a[7] += v0 * f.y;
        f = unpack_h2(h1.x); a[0] += v1 * f.x; a[1] += v1 * f.y;
        f = unpack_h2(h1.y); a[2] += v1 * f.x; a[3] += v1 * f.y;
        f = unpack_h2(h1.z); a[4] += v1 * f.x; a[5] += v1 * f.y;
        f = unpack_h2(h1.w); a[6] += v1 * f.x; a[7] += v1 * f.y;
    }
    if (j < end) {
        int2  e0 = g_edge[j];
        uint4 h0 = x[e0.x * 8 + c];
        float v0 = __int_as_float(e0.y);
        float2 f;
        f = unpack_h2(h0.x); a[0] += v0 * f.x; a[1] += v0 * f.y;
        f = unpack_h2(h0.y); a[2] += v0 * f.x; a[3] += v0 * f.y;
        f = unpack_h2(h0.z); a[4] += v0 * f.x; a[5] += v0 * f.y;
        f = unpack_h2(h0.w); a[6] += v0 * f.x; a[7] += v0 * f.y;
    }

    #pragma unroll
    for (int k = 0; k < 8; k++) {
        a[k] += __shfl_xor_sync(0xFFFFFFFFu, a[k], 8);
        a[k] += __shfl_xor_sync(0xFFFFFFFFu, a[k], 16);
    }
    if (slot == 0) {
        uint4 o;
        o.x = pack_h2(a[0], a[1]);
        o.y = pack_h2(a[2], a[3]);
        o.z = pack_h2(a[4], a[5]);
        o.w = pack_h2(a[6], a[7]);
        y[node * 8 + c] = o;
    }
}

// ---------------- fused layer-3 gather + dot ----------------
__device__ __forceinline__ void gather3_chunk(const uint4* __restrict__ x2,
                                              int node, int c, int slot,
                                              float (&g)[8]) {
    int beg = g_rowptr[node];
    int end = g_rowptr[node + 1];
    #pragma unroll
    for (int k = 0; k < 8; k++) g[k] = 0.f;
    for (int j = beg + slot; j < end; j += 4) {
        int2  ed = g_edge[j];
        float v  = __int_as_float(ed.y);
        uint4 h  = x2[ed.x * 8 + c];
        float2 f;
        f = unpack_h2(h.x); g[0] += v * f.x; g[1] += v * f.y;
        f = unpack_h2(h.y); g[2] += v * f.x; g[3] += v * f.y;
        f = unpack_h2(h.z); g[4] += v * f.x; g[5] += v * f.y;
        f = unpack_h2(h.w); g[6] += v * f.x; g[7] += v * f.y;
    }
    #pragma unroll
    for (int k = 0; k < 8; k++) {
        g[k] += __shfl_xor_sync(0xFFFFFFFFu, g[k], 8);
        g[k] += __shfl_xor_sync(0xFFFFFFFFu, g[k], 16);
    }
}

__global__ void dot_fused_kernel(const int* __restrict__ users,
                                 const int* __restrict__ items,
                                 const float* __restrict__ eu,
                                 const float* __restrict__ ei,
                                 float* __restrict__ out) {
    int b = blockIdx.x * (blockDim.x >> 5) + (threadIdx.x >> 5);
    if (b >= BATCH) return;
    int lane = threadIdx.x & 31;
    int c    = lane & 7;
    int slot = lane >> 3;

    int u  = users[b];
    int im = items[b];
    int ni = N_USERS + im;

    float gu[8], gi[8];
    gather3_chunk(g_x2, u,  c, slot, gu);
    gather3_chunk(g_x2, ni, c, slot, gi);

    const float4* pu = reinterpret_cast<const float4*>(eu + u  * DIM + c * 8);
    const float4* pi = reinterpret_cast<const float4*>(ei + im * DIM + c * 8);
    float4 bu0 = pu[0], bu1 = pu[1];
    float4 bi0 = pi[0], bi1 = pi[1];

    uint4 u1h = g_x1[u  * 8 + c], u2h = g_x2[u  * 8 + c];
    uint4 i1h = g_x1[ni * 8 + c], i2h = g_x2[ni * 8 + c];

    float ru[8], ri[8];
    {
        float2 t;
        t = unpack_h2(u1h.x); ru[0] = bu0.x + t.x; ru[1] = bu0.y + t.y;
        t = unpack_h2(u1h.y); ru[2] = bu0.z + t.x; ru[3] = bu0.w + t.y;
        t = unpack_h2(u1h.z); ru[4] = bu1.x + t.x; ru[5] = bu1.y + t.y;
        t = unpack_h2(u1h.w); ru[6] = bu1.z + t.x; ru[7] = bu1.w + t.y;
        t = unpack_h2(u2h.x); ru[0] += t.x; ru[1] += t.y;
        t = unpack_h2(u2h.y); ru[2] += t.x; ru[3] += t.y;
        t = unpack_h2(u2h.z); ru[4] += t.x; ru[5] += t.y;
        t = unpack_h2(u2h.w); ru[6] += t.x; ru[7] += t.y;

        t = unpack_h2(i1h.x); ri[0] = bi0.x + t.x; ri[1] = bi0.y + t.y;
        t = unpack_h2(i1h.y); ri[2] = bi0.z + t.x; ri[3] = bi0.w + t.y;
        t = unpack_h2(i1h.z); ri[4] = bi1.x + t.x; ri[5] = bi1.y + t.y;
        t = unpack_h2(i1h.w); ri[6] = bi1.z + t.x; ri[7] = bi1.w + t.y;
        t = unpack_h2(i2h.x); ri[0] += t.x; ri[1] += t.y;
        t = unpack_h2(i2h.y); ri[2] += t.x; ri[3] += t.y;
        t = unpack_h2(i2h.z); ri[4] += t.x; ri[5] += t.y;
        t = unpack_h2(i2h.w); ri[6] += t.x; ri[7] += t.y;
    }

    float p = 0.f;
    #pragma unroll
    for (int k = 0; k < 8; k++)
        p += (ru[k] + gu[k]) * (ri[k] + gi[k]);

    p += __shfl_xor_sync(0xFFFFFFFFu, p, 1);
    p += __shfl_xor_sync(0xFFFFFFFFu, p, 2);
    p += __shfl_xor_sync(0xFFFFFFFFu, p, 4);

    if (lane == 0)
        out[b] = p * (1.0f / 16.0f);     // (1/4)^2 mean-pool factors
}

// ---------------- launch ----------------
extern "C" void kernel_launch(void* const* d_in, const int* in_sizes, int n_in,
                              void* d_out, int out_size) {
    (void)in_sizes; (void)n_in; (void)out_size;
    const float* emb_user = (const float*)d_in[0];
    const float* emb_item = (const float*)d_in[1];
    const float* vals     = (const float*)d_in[2];
    const int*   src      = (const int*)  d_in[3];
    const int*   dst      = (const int*)  d_in[4];
    const int*   users    = (const int*)  d_in[5];
    const int*   items    = (const int*)  d_in[6];
    float* out = (float*)d_out;

    uint4 *e16, *x1, *x2;
    cudaGetSymbolAddress((void**)&e16, g_e16);
    cudaGetSymbolAddress((void**)&x1,  g_x1);
    cudaGetSymbolAddress((void**)&x2,  g_x2);

    const int T = 256;
    const int grid_cvt  = (TOT8 + T - 1) / T;
    const int grid_e4   = ((N_EDGES / 4) + T - 1) / T;

    // 1: convert emb -> fp16, zero cnt + scan state
    convert_kernel<<<grid_cvt, T>>>(emb_user, emb_item);
    // 2: histogram
    hist_kernel<<<grid_e4, T>>>(dst);
    // 3: one-pass scan -> rowptr
    scan_kernel<<<NBLK, SCAN_B>>>();
    // 4: scatter into dst-grouped edge array (countdown on cnt)
    scatter_kernel<<<grid_e4, T>>>(src, dst, vals);

    // 5,6: propagation (fp16 gather, fp32 accumulate)
    const int wpb = T / 32;
    const int grid_spmm = (N_NODES + wpb - 1) / wpb;
    spmm_half_kernel<<<grid_spmm, T>>>(e16, x1);   // layer 1
    spmm_half_kernel<<<grid_spmm, T>>>(x1,  x2);   // layer 2 (ncu -s 5 profiles this)

    // 7: layer 3 fused with batched dot
    const int grid_dot = (BATCH + wpb - 1) / wpb;
    dot_fused_kernel<<<grid_dot, T>>>(users, items, emb_user, emb_item, out);
}